// round 7
// baseline (speedup 1.0000x reference)
#include <cuda_runtime.h>
#include <math.h>

// Shapelet_66932770341112 on sm_103a
// B=16, C=8, T=512, L=24, STRIDE=2, N=64, M=245, EPS=1
// d(b,m,n,c) = (1/L) * sum_l |x[b,c,2m+l] - w[n,c,l]| * pcm[c,m]
// out[0 : B*N*C]       = exp(-min_m d^2) = exp(-(min_m |d|)^2)
// out[B*N*C : 2*B*N*C] = min_m d

#define BB 16
#define CC 8
#define TT 512
#define LL 24
#define NN 64
#define MM 245
#define NBLK 8             // n per block

typedef unsigned long long ull;

__device__ __forceinline__ ull add_f32x2(ull a, ull b) {
    ull r;
    asm("add.rn.f32x2 %0, %1, %2;" : "=l"(r) : "l"(a), "l"(b));
    return r;
}
__device__ __forceinline__ float lo32(ull v) { return __int_as_float((unsigned)(v & 0xffffffffULL)); }
__device__ __forceinline__ float hi32(ull v) { return __int_as_float((unsigned)(v >> 32)); }
// swizzle pair-index -> physical slot; breaks stride-2 bank conflicts
__device__ __forceinline__ int swz(int i) { return i + (i >> 3); }

__global__ __launch_bounds__(128, 8)
void shapelet_kernel(const float* __restrict__ x,
                     const float* __restrict__ w,
                     const float* __restrict__ pcm,
                     float* __restrict__ out)
{
    // x row as (even,odd) float2 pairs, swizzled: pair(t) at xsm[swz(t)].
    __shared__ ull    xsm[304];            // swz(266)=299 max
    __shared__ ull    wneg[NBLK][12];      // 8 shapelets, negated, as pairs
    __shared__ float2 dsm[NBLK][128];      // per-(n, m-pair) (dmin, min|d|)

    const int bc    = blockIdx.x;          // b*C + c
    const int b     = bc >> 3;
    const int c     = bc & 7;
    const int n0    = blockIdx.y * NBLK;   // first shapelet of this block
    const int tid   = threadIdx.x;         // 0..127 == mpair
    const int lane  = tid & 31;
    const int warp  = tid >> 5;            // 0..3

    // ---- x row: 256 float2 pairs (swizzled) + zero pad to index 266 ----
    {
        const float2* xrow = (const float2*)(x + bc * TT);
        ((float2*)xsm)[swz(tid)]       = xrow[tid];
        ((float2*)xsm)[swz(tid + 128)] = xrow[tid + 128];
        if (tid < 11) ((float2*)xsm)[swz(256 + tid)] = make_float2(0.f, 0.f);
    }
    // ---- 8 shapelets' weights for channel c, negated (192 floats) ----
    for (int i = tid; i < NBLK * LL; i += 128) {
        const int j = i / LL;
        const int l = i % LL;
        ((float*)wneg)[j * LL + l] = -w[((n0 + j) * CC + c) * LL + l];
    }
    __syncthreads();

    // ---- register window covering m0 = 2*tid and m0+1: xw[k] = pair(m0+k) ----
    const int m0 = 2 * tid;
    ull xw[13];
#pragma unroll
    for (int k = 0; k < 13; ++k) xw[k] = xsm[swz(m0 + k)];

    const float INF = __int_as_float(0x7f800000);
    const float pen0   = (m0     < MM) ? pcm[c * MM + m0]     * (1.0f / (float)LL) : 0.0f;
    const float pen1   = (m0 + 1 < MM) ? pcm[c * MM + m0 + 1] * (1.0f / (float)LL) : 0.0f;
    const float guard0 = (m0     < MM) ? 0.0f : INF;
    const float guard1 = (m0 + 1 < MM) ? 0.0f : INF;

    const ull ABS2 = 0x7fffffff7fffffffULL;

#pragma unroll
    for (int j = 0; j < NBLK; ++j) {
        const ulonglong2* wp = (const ulonglong2*)wneg[j];
        ull a0 = 0ULL, a1 = 0ULL, b0 = 0ULL, b1 = 0ULL;   // 4 independent chains
#pragma unroll
        for (int k = 0; k < 6; ++k) {
            const ulonglong2 wv = wp[k];                  // weight pairs 2k, 2k+1
            a0 = add_f32x2(a0, add_f32x2(xw[2 * k],     wv.x) & ABS2);  // m0,  wp 2k
            b0 = add_f32x2(b0, add_f32x2(xw[2 * k + 1], wv.x) & ABS2);  // m0+1,wp 2k
            a1 = add_f32x2(a1, add_f32x2(xw[2 * k + 1], wv.y) & ABS2);  // m0,  wp 2k+1
            b1 = add_f32x2(b1, add_f32x2(xw[2 * k + 2], wv.y) & ABS2);  // m0+1,wp 2k+1
        }
        a0 = add_f32x2(a0, a1);
        b0 = add_f32x2(b0, b1);
        const float s0 = lo32(a0) + hi32(a0);
        const float s1 = lo32(b0) + hi32(b0);
        const float d0 = fmaf(s0, pen0, guard0);
        const float d1 = fmaf(s1, pen1, guard1);
        // FMNMX with |src| modifiers: min|d| is free of explicit squares
        dsm[j][tid] = make_float2(fminf(d0, d1),
                                  fminf(fabsf(d0), fabsf(d1)));
    }
    __syncthreads();

    // ---- 4 warps reduce 8 rows (warp w -> rows w, w+4) ----
#pragma unroll
    for (int rr = 0; rr < 2; ++rr) {
        const int r = warp + rr * 4;
        float mn = INF, mna = INF;
#pragma unroll
        for (int i = 0; i < 4; ++i) {
            const float2 v = dsm[r][lane + i * 32];
            mn  = fminf(mn,  v.x);
            mna = fminf(mna, v.y);
        }
#pragma unroll
        for (int off = 16; off; off >>= 1) {
            mn  = fminf(mn,  __shfl_xor_sync(0xffffffffu, mn,  off));
            mna = fminf(mna, __shfl_xor_sync(0xffffffffu, mna, off));
        }
        if (lane == 0) {
            const int n = n0 + r;
            const int o = (b * NN + n) * CC + c;
            out[o] = expf(-(mna * mna));
            out[BB * NN * CC + o] = mn;
        }
    }
}

extern "C" void kernel_launch(void* const* d_in, const int* in_sizes, int n_in,
                              void* d_out, int out_size)
{
    const float* x   = (const float*)d_in[0];   // (B, C, T)
    const float* w   = (const float*)d_in[1];   // (N, C, L)
    const float* pcm = (const float*)d_in[2];   // (C, M)
    float* out = (float*)d_out;

    dim3 grid(BB * CC, NN / NBLK);              // 128 x 8 = 1024 blocks of 128 thr
    shapelet_kernel<<<grid, 128>>>(x, w, pcm, out);
}

// round 8
// speedup vs baseline: 1.1463x; 1.1463x over previous
#include <cuda_runtime.h>
#include <math.h>

// Shapelet_66932770341112 on sm_103a
// B=16, C=8, T=512, L=24, STRIDE=2, N=64, M=245, EPS=1
// d(b,m,n,c) = (1/L) * sum_l |x[b,c,2m+l] - w[n,c,l]| * pcm[c,m]
// out[0 : B*N*C]       = exp(-(min_m |d|)^2)
// out[B*N*C : 2*B*N*C] = min_m d

#define BB 16
#define CC 8
#define TT 512
#define LL 24
#define NN 64
#define MM 245
#define NBLK 8             // n per block

typedef unsigned long long ull;

__device__ __forceinline__ ull add_f32x2(ull a, ull b) {
    ull r;
    asm("add.rn.f32x2 %0, %1, %2;" : "=l"(r) : "l"(a), "l"(b));
    return r;
}
__device__ __forceinline__ float lo32(ull v) { return __int_as_float((unsigned)(v & 0xffffffffULL)); }
__device__ __forceinline__ float hi32(ull v) { return __int_as_float((unsigned)(v >> 32)); }
// swizzle pair-index -> physical slot; breaks stride-2 bank conflicts
__device__ __forceinline__ int swz(int i) { return i + (i >> 3); }

__global__ __launch_bounds__(128, 8)
void shapelet_kernel(const float* __restrict__ x,
                     const float* __restrict__ w,
                     const float* __restrict__ pcm,
                     float* __restrict__ out)
{
    __shared__ ull    xsm[304];            // swizzled x pairs
    __shared__ ull    wneg[NBLK][12];      // 8 shapelets, negated, as pairs
    __shared__ float2 dsm[NBLK][128];      // per-(n, m-pair) (dmin, min|d|)

    const int bc    = blockIdx.x;          // b*C + c
    const int b     = bc >> 3;
    const int c     = bc & 7;
    const int n0    = blockIdx.y * NBLK;
    const int tid   = threadIdx.x;         // 0..127 == m-pair index
    const int lane  = tid & 31;
    const int warp  = tid >> 5;

    // ---- x row: 256 float2 pairs (swizzled) + zero pad ----
    {
        const float2* xrow = (const float2*)(x + bc * TT);
        ((float2*)xsm)[swz(tid)]       = xrow[tid];
        ((float2*)xsm)[swz(tid + 128)] = xrow[tid + 128];
        if (tid < 11) ((float2*)xsm)[swz(256 + tid)] = make_float2(0.f, 0.f);
    }
    // ---- 8 shapelets' weights for channel c, negated (192 floats) ----
    for (int i = tid; i < NBLK * LL; i += 128) {
        const int j = i / LL;
        const int l = i % LL;
        ((float*)wneg)[j * LL + l] = -w[((n0 + j) * CC + c) * LL + l];
    }
    __syncthreads();

    // ---- register window covering m0 = 2*tid and m0+1: xw[k] = pair(m0+k) ----
    const int m0 = 2 * tid;
    ull xw[13];
#pragma unroll
    for (int k = 0; k < 13; ++k) xw[k] = xsm[swz(m0 + k)];

    const float INF = __int_as_float(0x7f800000);
    const float pen0   = (m0     < MM) ? pcm[c * MM + m0]     * (1.0f / (float)LL) : 0.0f;
    const float pen1   = (m0 + 1 < MM) ? pcm[c * MM + m0 + 1] * (1.0f / (float)LL) : 0.0f;
    const float guard0 = (m0     < MM) ? 0.0f : INF;
    const float guard1 = (m0 + 1 < MM) ? 0.0f : INF;

#pragma unroll
    for (int j = 0; j < NBLK; ++j) {
        const ulonglong2* wp = (const ulonglong2*)wneg[j];
        // 4 scalar accumulator chains per m (8 total); abs is a free |src|
        // modifier on the accumulating FADD.
        float a0 = 0.f, a1 = 0.f, a2 = 0.f, a3 = 0.f;   // m0
        float b0 = 0.f, b1 = 0.f, b2 = 0.f, b3 = 0.f;   // m0+1
#pragma unroll
        for (int k = 0; k < 6; ++k) {
            const ulonglong2 wv = wp[k];                 // weight pairs 2k, 2k+1
            const ull t0 = add_f32x2(xw[2 * k],     wv.x);  // m0,   wpair 2k
            const ull t1 = add_f32x2(xw[2 * k + 1], wv.y);  // m0,   wpair 2k+1
            const ull u0 = add_f32x2(xw[2 * k + 1], wv.x);  // m0+1, wpair 2k
            const ull u1 = add_f32x2(xw[2 * k + 2], wv.y);  // m0+1, wpair 2k+1
            a0 += fabsf(lo32(t0));  a1 += fabsf(hi32(t0));
            a2 += fabsf(lo32(t1));  a3 += fabsf(hi32(t1));
            b0 += fabsf(lo32(u0));  b1 += fabsf(hi32(u0));
            b2 += fabsf(lo32(u1));  b3 += fabsf(hi32(u1));
        }
        const float s0 = (a0 + a1) + (a2 + a3);
        const float s1 = (b0 + b1) + (b2 + b3);
        const float d0 = fmaf(s0, pen0, guard0);
        const float d1 = fmaf(s1, pen1, guard1);
        dsm[j][tid] = make_float2(fminf(d0, d1),
                                  fminf(fabsf(d0), fabsf(d1)));
    }
    __syncthreads();

    // ---- 4 warps reduce 8 rows (warp w -> rows w, w+4) ----
#pragma unroll
    for (int rr = 0; rr < 2; ++rr) {
        const int r = warp + rr * 4;
        float mn = INF, mna = INF;
#pragma unroll
        for (int i = 0; i < 4; ++i) {
            const float2 v = dsm[r][lane + i * 32];
            mn  = fminf(mn,  v.x);
            mna = fminf(mna, v.y);
        }
#pragma unroll
        for (int off = 16; off; off >>= 1) {
            mn  = fminf(mn,  __shfl_xor_sync(0xffffffffu, mn,  off));
            mna = fminf(mna, __shfl_xor_sync(0xffffffffu, mna, off));
        }
        if (lane == 0) {
            const int n = n0 + r;
            const int o = (b * NN + n) * CC + c;
            out[o] = expf(-(mna * mna));
            out[BB * NN * CC + o] = mn;
        }
    }
}

extern "C" void kernel_launch(void* const* d_in, const int* in_sizes, int n_in,
                              void* d_out, int out_size)
{
    const float* x   = (const float*)d_in[0];   // (B, C, T)
    const float* w   = (const float*)d_in[1];   // (N, C, L)
    const float* pcm = (const float*)d_in[2];   // (C, M)
    float* out = (float*)d_out;

    dim3 grid(BB * CC, NN / NBLK);              // 128 x 8 = 1024 blocks of 128 thr
    shapelet_kernel<<<grid, 128>>>(x, w, pcm, out);
}